// round 3
// baseline (speedup 1.0000x reference)
#include <cuda_runtime.h>

#define B_ 2
#define N_ 16384
#define S_ 4096
#define K_ 32
#define C0 67
#define C1 64
#define C2 64
#define C3 128
#define ST 36
#define FULLM 0xffffffffu
#define FINF 3.402823466e38f

typedef unsigned long long ull;

__device__ __forceinline__ ull fma2(ull a, ull b, ull c){
    ull d;
    asm("fma.rn.f32x2 %0, %1, %2, %3;" : "=l"(d) : "l"(a), "l"(b), "l"(c));
    return d;
}
__device__ __forceinline__ ull pk(float lo, float hi){
    ull r; asm("mov.b64 %0, {%1,%2};" : "=l"(r) : "f"(lo), "f"(hi)); return r;
}
__device__ __forceinline__ float2 upk(ull v){
    float2 f; asm("mov.b64 {%0,%1}, %2;" : "=f"(f.x), "=f"(f.y) : "l"(v)); return f;
}

// ---------------- scratch ----------------
__device__ __align__(16) float  d_pt[B_*N_*C1];
__device__ __align__(16) float4 d_xyz4[B_*N_];
__device__              int     d_knn[B_*S_*K_];
__device__ __align__(16) float  d_buf0[(size_t)B_*S_*C1*K_];
__device__ __align__(16) float  d_buf1[(size_t)B_*S_*C2*K_];
__device__              float   d_maxb[B_*S_*C3];
__device__              float   d_minb[B_*S_*C3];
__device__              float   d_ps0[4096*C1], d_pq0[4096*C1];
__device__              float   d_ps1[4096*C2], d_pq1[4096*C2];
__device__              float   d_ps2[8192*C3], d_pq2[8192*C3];
__device__              float   d_mean0[C1], d_istd0[C1];
__device__              float   d_mean1[C2], d_istd1[C2];
__device__              float   d_mean2[C3], d_istd2[C3];

// ---------------- transpose points ----------------
__global__ void k_tr(const float* __restrict__ pts){
    __shared__ float tile[32][33];
    int b = blockIdx.z, c0 = blockIdx.y*32, n0 = blockIdx.x*32;
    for (int j = threadIdx.y; j < 32; j += 8)
        tile[j][threadIdx.x] = pts[((size_t)(b*C1 + c0 + j))*N_ + n0 + threadIdx.x];
    __syncthreads();
    for (int j = threadIdx.y; j < 32; j += 8)
        d_pt[((size_t)(b*N_ + n0 + j))*C1 + c0 + threadIdx.x] = tile[threadIdx.x][j];
}

// ---------------- xyz4 + new_xyz ----------------
__global__ void k_xyz(const float* __restrict__ xyz, float* __restrict__ out){
    int i = blockIdx.x*blockDim.x + threadIdx.x;
    if (i >= B_*N_) return;
    int b = i / N_, n = i % N_;
    float x = xyz[(b*3+0)*N_+n], y = xyz[(b*3+1)*N_+n], z = xyz[(b*3+2)*N_+n];
    d_xyz4[i] = make_float4(x, y, z, fmaf(z,z, fmaf(y,y, x*x)));
    if (n < S_){
        out[(b*3+0)*S_+n] = x;
        out[(b*3+1)*S_+n] = y;
        out[(b*3+2)*S_+n] = z;
    }
}

// ---------------- KNN: warp handles 4 queries; candidates loaded once ----------------
__global__ void k_knn(){
    int wg   = (blockIdx.x*blockDim.x + threadIdx.x) >> 5;   // global warp id
    int lane = threadIdx.x & 31;
    int q0g  = wg*4;                 // global query base (4 per warp, same batch)
    int b = q0g / S_;
    int q0 = q0g - b*S_;
    const float4* base = &d_xyz4[b*N_];

    float cx[4], cy[4], cz[4], cs[4];
    #pragma unroll
    for (int q = 0; q < 4; q++){
        float4 c4 = base[q0 + q];
        cx[q]=c4.x; cy[q]=c4.y; cz[q]=c4.z; cs[q]=c4.w;
    }

    float bd[4] = {FINF,FINF,FINF,FINF};
    int   bi[4] = {0,0,0,0};
    float cm[4] = {FINF,FINF,FINF,FINF};

    for (int j = 0; j < N_/32; j++){
        float4 p = base[j*32 + lane];
        #pragma unroll
        for (int q = 0; q < 4; q++){
            float d = (cs[q] + p.w) - 2.0f*fmaf(cz[q],p.z, fmaf(cy[q],p.y, cx[q]*p.x));
            unsigned m = __ballot_sync(FULLM, d < cm[q]);
            while (m){
                int src = __ffs(m) - 1; m &= m - 1;
                float cd = __shfl_sync(FULLM, d, src);
                if (cd < cm[q]){
                    int cn = j*32 + src;
                    float pk_ = __shfl_up_sync(FULLM, bd[q], 1);
                    int   pi_ = __shfl_up_sync(FULLM, bi[q], 1);
                    bool shift = (bd[q] > cd);           // strict: stable vs ties
                    unsigned sm_ = __ballot_sync(FULLM, shift);
                    int first = __ffs(sm_) - 1;
                    if (shift){
                        if (lane == first){ bd[q] = cd; bi[q] = cn; }
                        else              { bd[q] = pk_; bi[q] = pi_; }
                    }
                    cm[q] = __shfl_sync(FULLM, bd[q], 31);
                }
            }
        }
    }
    #pragma unroll
    for (int q = 0; q < 4; q++)
        d_knn[(q0g + q)*K_ + lane] = bi[q];
}

// ---------------- layer0: gather + GEMM, 8x8 tile per thread, warp per point ----------------
__global__ void __launch_bounds__(128, 4) k_g0(const float* __restrict__ W0g){
    extern __shared__ float dyn[];
    float* sx = dyn;                 // 4 * C0 * ST
    float* sw = dyn + 4*C0*ST;       // C0 * 64
    __shared__ float ssum[C1], ssq[C1];
    int t = threadIdx.x;
    int bs0 = blockIdx.x*4;

    for (int e = t; e < C0*64; e += 128){
        int ci = e >> 6, co = e & 63;
        sw[e] = W0g[co*C0 + ci];
    }
    if (t < C1){ ssum[t] = 0.f; ssq[t] = 0.f; }

    { // gather: 1 thread per (point, k)
        int s_l = t >> 5, k = t & 31;
        int bs = bs0 + s_l;
        int b = bs / S_, s = bs % S_;
        int idx = d_knn[bs*K_ + k];
        float* xr = &sx[s_l*C0*ST];
        float4 pc = d_xyz4[b*N_ + s];
        float4 pn = d_xyz4[b*N_ + idx];
        xr[0*ST + k] = pn.x - pc.x;
        xr[1*ST + k] = pn.y - pc.y;
        xr[2*ST + k] = pn.z - pc.z;
        const float4* prow = (const float4*)&d_pt[((size_t)(b*N_ + idx))*C1];
        #pragma unroll
        for (int q = 0; q < 16; q++){
            float4 v = prow[q];
            int c = 3 + q*4;
            xr[(c+0)*ST + k] = v.x;
            xr[(c+1)*ST + k] = v.y;
            xr[(c+2)*ST + k] = v.z;
            xr[(c+3)*ST + k] = v.w;
        }
    }
    __syncthreads();

    int lane = t & 31, wp = t >> 5;
    int kq = lane & 3, cog = lane >> 2;
    const float* xb_ = &sx[wp*C0*ST + kq*8];
    const float* wb_ = sw + cog*8;
    ull acc[8][4];
    #pragma unroll
    for (int j = 0; j < 8; j++){ acc[j][0]=0; acc[j][1]=0; acc[j][2]=0; acc[j][3]=0; }

    #pragma unroll 2
    for (int ci = 0; ci < C0; ci++){
        float4 xa = *(const float4*)(xb_ + ci*ST);
        float4 xc = *(const float4*)(xb_ + ci*ST + 4);
        ull x0 = pk(xa.x,xa.y), x1 = pk(xa.z,xa.w);
        ull x2 = pk(xc.x,xc.y), x3 = pk(xc.z,xc.w);
        float4 wa = *(const float4*)(wb_ + ci*64);
        float4 wc = *(const float4*)(wb_ + ci*64 + 4);
        float wv[8] = {wa.x,wa.y,wa.z,wa.w, wc.x,wc.y,wc.z,wc.w};
        #pragma unroll
        for (int j = 0; j < 8; j++){
            ull w2 = pk(wv[j], wv[j]);
            acc[j][0] = fma2(w2, x0, acc[j][0]);
            acc[j][1] = fma2(w2, x1, acc[j][1]);
            acc[j][2] = fma2(w2, x2, acc[j][2]);
            acc[j][3] = fma2(w2, x3, acc[j][3]);
        }
    }

    int bs = bs0 + wp;
    float* orow = &d_buf0[(size_t)bs*C1*K_];
    float ls[8], lq[8];
    #pragma unroll
    for (int j = 0; j < 8; j++){
        float2 a0 = upk(acc[j][0]), a1 = upk(acc[j][1]);
        float2 a2 = upk(acc[j][2]), a3 = upk(acc[j][3]);
        *(float4*)&orow[(cog*8+j)*K_ + kq*8]     = make_float4(a0.x,a0.y,a1.x,a1.y);
        *(float4*)&orow[(cog*8+j)*K_ + kq*8 + 4] = make_float4(a2.x,a2.y,a3.x,a3.y);
        ls[j] = ((a0.x+a0.y)+(a1.x+a1.y)) + ((a2.x+a2.y)+(a3.x+a3.y));
        float q0 = fmaf(a0.x,a0.x, fmaf(a0.y,a0.y, fmaf(a1.x,a1.x, a1.y*a1.y)));
        lq[j] = fmaf(a2.x,a2.x, fmaf(a2.y,a2.y, fmaf(a3.x,a3.x, fmaf(a3.y,a3.y, q0))));
    }
    #pragma unroll
    for (int j = 0; j < 8; j++){
        ls[j] += __shfl_xor_sync(FULLM, ls[j], 1);
        ls[j] += __shfl_xor_sync(FULLM, ls[j], 2);
        lq[j] += __shfl_xor_sync(FULLM, lq[j], 1);
        lq[j] += __shfl_xor_sync(FULLM, lq[j], 2);
    }
    if (kq == 0){
        #pragma unroll
        for (int j = 0; j < 8; j++){
            atomicAdd(&ssum[cog*8+j], ls[j]);
            atomicAdd(&ssq [cog*8+j], lq[j]);
        }
    }
    __syncthreads();
    if (t < C1){
        d_ps0[blockIdx.x*C1 + t] = ssum[t];
        d_pq0[blockIdx.x*C1 + t] = ssq[t];
    }
}

// ---------------- stats finalize ----------------
__global__ void k_stats(int which){
    const float *ps, *pq; float *mean, *istd; int nblk, C;
    if (which == 0){ ps = d_ps0; pq = d_pq0; mean = d_mean0; istd = d_istd0; nblk = 2048; C = 64; }
    else if (which == 1){ ps = d_ps1; pq = d_pq1; mean = d_mean1; istd = d_istd1; nblk = 2048; C = 64; }
    else { ps = d_ps2; pq = d_pq2; mean = d_mean2; istd = d_istd2; nblk = 4096; C = 128; }
    int c = blockIdx.x;
    __shared__ float rs[256], rq[256];
    float s = 0.f, q = 0.f;
    for (int i = threadIdx.x; i < nblk; i += 256){ s += ps[i*C + c]; q += pq[i*C + c]; }
    rs[threadIdx.x] = s; rq[threadIdx.x] = q;
    __syncthreads();
    for (int o = 128; o; o >>= 1){
        if (threadIdx.x < o){ rs[threadIdx.x] += rs[threadIdx.x+o]; rq[threadIdx.x] += rq[threadIdx.x+o]; }
        __syncthreads();
    }
    if (threadIdx.x == 0){
        float cnt = (float)(B_*S_*K_);
        float m = rs[0] / cnt;
        float v = rq[0] / cnt - m*m;
        mean[c] = m;
        istd[c] = rsqrtf(v + 1e-5f);
    }
}

// ---------------- layer1 ----------------
__global__ void __launch_bounds__(128, 4) k_g1(const float* __restrict__ W1g,
                     const float* __restrict__ g0, const float* __restrict__ b0){
    extern __shared__ float dyn[];
    float* sx = dyn;                 // 4 * C1 * ST
    float* sw = dyn + 4*C1*ST;       // C1 * 64
    __shared__ float ssum[C2], ssq[C2], sa[C1], sb[C1];
    int t = threadIdx.x;
    int bs0 = blockIdx.x*4;

    for (int e = t; e < C1*64; e += 128){
        int ci = e >> 6, co = e & 63;
        sw[e] = W1g[co*C1 + ci];
    }
    if (t < C1){
        float a = d_istd0[t]*g0[t];
        sa[t] = a;
        sb[t] = fmaf(-d_mean0[t], a, b0[t]);
        ssum[t] = 0.f; ssq[t] = 0.f;
    }
    __syncthreads();

    {
        const float4* src = (const float4*)&d_buf0[(size_t)bs0*C1*K_];
        for (int e = t; e < 2048; e += 128){
            float4 v = src[e];
            int p = e >> 9, r2 = e & 511;
            int ci = r2 >> 3, k4 = (r2 & 7)*4;
            float a = sa[ci], bb = sb[ci], r;
            r = fmaf(v.x,a,bb); v.x = r >= 0.f ? r : 0.1f*r;
            r = fmaf(v.y,a,bb); v.y = r >= 0.f ? r : 0.1f*r;
            r = fmaf(v.z,a,bb); v.z = r >= 0.f ? r : 0.1f*r;
            r = fmaf(v.w,a,bb); v.w = r >= 0.f ? r : 0.1f*r;
            *(float4*)&sx[p*C1*ST + ci*ST + k4] = v;
        }
    }
    __syncthreads();

    int lane = t & 31, wp = t >> 5;
    int kq = lane & 3, cog = lane >> 2;
    const float* xb_ = &sx[wp*C1*ST + kq*8];
    const float* wb_ = sw + cog*8;
    ull acc[8][4];
    #pragma unroll
    for (int j = 0; j < 8; j++){ acc[j][0]=0; acc[j][1]=0; acc[j][2]=0; acc[j][3]=0; }

    #pragma unroll 2
    for (int ci = 0; ci < C1; ci++){
        float4 xa = *(const float4*)(xb_ + ci*ST);
        float4 xc = *(const float4*)(xb_ + ci*ST + 4);
        ull x0 = pk(xa.x,xa.y), x1 = pk(xa.z,xa.w);
        ull x2 = pk(xc.x,xc.y), x3 = pk(xc.z,xc.w);
        float4 wa = *(const float4*)(wb_ + ci*64);
        float4 wc = *(const float4*)(wb_ + ci*64 + 4);
        float wv[8] = {wa.x,wa.y,wa.z,wa.w, wc.x,wc.y,wc.z,wc.w};
        #pragma unroll
        for (int j = 0; j < 8; j++){
            ull w2 = pk(wv[j], wv[j]);
            acc[j][0] = fma2(w2, x0, acc[j][0]);
            acc[j][1] = fma2(w2, x1, acc[j][1]);
            acc[j][2] = fma2(w2, x2, acc[j][2]);
            acc[j][3] = fma2(w2, x3, acc[j][3]);
        }
    }

    int bs = bs0 + wp;
    float* orow = &d_buf1[(size_t)bs*C2*K_];
    float ls[8], lq[8];
    #pragma unroll
    for (int j = 0; j < 8; j++){
        float2 a0 = upk(acc[j][0]), a1 = upk(acc[j][1]);
        float2 a2 = upk(acc[j][2]), a3 = upk(acc[j][3]);
        *(float4*)&orow[(cog*8+j)*K_ + kq*8]     = make_float4(a0.x,a0.y,a1.x,a1.y);
        *(float4*)&orow[(cog*8+j)*K_ + kq*8 + 4] = make_float4(a2.x,a2.y,a3.x,a3.y);
        ls[j] = ((a0.x+a0.y)+(a1.x+a1.y)) + ((a2.x+a2.y)+(a3.x+a3.y));
        float q0 = fmaf(a0.x,a0.x, fmaf(a0.y,a0.y, fmaf(a1.x,a1.x, a1.y*a1.y)));
        lq[j] = fmaf(a2.x,a2.x, fmaf(a2.y,a2.y, fmaf(a3.x,a3.x, fmaf(a3.y,a3.y, q0))));
    }
    #pragma unroll
    for (int j = 0; j < 8; j++){
        ls[j] += __shfl_xor_sync(FULLM, ls[j], 1);
        ls[j] += __shfl_xor_sync(FULLM, ls[j], 2);
        lq[j] += __shfl_xor_sync(FULLM, lq[j], 1);
        lq[j] += __shfl_xor_sync(FULLM, lq[j], 2);
    }
    if (kq == 0){
        #pragma unroll
        for (int j = 0; j < 8; j++){
            atomicAdd(&ssum[cog*8+j], ls[j]);
            atomicAdd(&ssq [cog*8+j], lq[j]);
        }
    }
    __syncthreads();
    if (t < C2){
        d_ps1[blockIdx.x*C2 + t] = ssum[t];
        d_pq1[blockIdx.x*C2 + t] = ssq[t];
    }
}

// ---------------- layer2: 2 points/block, 2 warps/point, max/min over k ----------------
__global__ void __launch_bounds__(128, 4) k_g2(const float* __restrict__ W2g,
                     const float* __restrict__ g1, const float* __restrict__ b1){
    extern __shared__ float dyn[];
    float* sx = dyn;                 // 2 * C2 * ST
    float* sw = dyn + 2*C2*ST;       // C2 * 128
    __shared__ float sa[C2], sb[C2], ssum[C3], ssq[C3];
    int t = threadIdx.x;
    int bs0 = blockIdx.x*2;

    for (int e = t; e < C2*C3; e += 128){
        int ci = e >> 7, co = e & 127;
        sw[e] = W2g[co*C2 + ci];
    }
    if (t < C2){
        float a = d_istd1[t]*g1[t];
        sa[t] = a;
        sb[t] = fmaf(-d_mean1[t], a, b1[t]);
    }
    if (t < C3){ ssum[t] = 0.f; ssq[t] = 0.f; }
    __syncthreads();

    {
        const float4* src = (const float4*)&d_buf1[(size_t)bs0*C2*K_];
        for (int e = t; e < 1024; e += 128){
            float4 v = src[e];
            int p = e >> 9, r2 = e & 511;
            int ci = r2 >> 3, k4 = (r2 & 7)*4;
            float a = sa[ci], bb = sb[ci], r;
            r = fmaf(v.x,a,bb); v.x = r >= 0.f ? r : 0.1f*r;
            r = fmaf(v.y,a,bb); v.y = r >= 0.f ? r : 0.1f*r;
            r = fmaf(v.z,a,bb); v.z = r >= 0.f ? r : 0.1f*r;
            r = fmaf(v.w,a,bb); v.w = r >= 0.f ? r : 0.1f*r;
            *(float4*)&sx[p*C2*ST + ci*ST + k4] = v;
        }
    }
    __syncthreads();

    int lane = t & 31, wp = t >> 5;
    int pt = wp >> 1, half = wp & 1;
    int kq = lane & 3, cog = lane >> 2;
    const float* xb_ = &sx[pt*C2*ST + kq*8];
    const float* wb_ = sw + half*64 + cog*8;
    ull acc[8][4];
    #pragma unroll
    for (int j = 0; j < 8; j++){ acc[j][0]=0; acc[j][1]=0; acc[j][2]=0; acc[j][3]=0; }

    #pragma unroll 2
    for (int ci = 0; ci < C2; ci++){
        float4 xa = *(const float4*)(xb_ + ci*ST);
        float4 xc = *(const float4*)(xb_ + ci*ST + 4);
        ull x0 = pk(xa.x,xa.y), x1 = pk(xa.z,xa.w);
        ull x2 = pk(xc.x,xc.y), x3 = pk(xc.z,xc.w);
        float4 wa = *(const float4*)(wb_ + ci*128);
        float4 wc = *(const float4*)(wb_ + ci*128 + 4);
        float wv[8] = {wa.x,wa.y,wa.z,wa.w, wc.x,wc.y,wc.z,wc.w};
        #pragma unroll
        for (int j = 0; j < 8; j++){
            ull w2 = pk(wv[j], wv[j]);
            acc[j][0] = fma2(w2, x0, acc[j][0]);
            acc[j][1] = fma2(w2, x1, acc[j][1]);
            acc[j][2] = fma2(w2, x2, acc[j][2]);
            acc[j][3] = fma2(w2, x3, acc[j][3]);
        }
    }

    int bs = bs0 + pt;
    float lmx[8], lmn[8], ls[8], lq[8];
    #pragma unroll
    for (int j = 0; j < 8; j++){
        float2 a0 = upk(acc[j][0]), a1 = upk(acc[j][1]);
        float2 a2 = upk(acc[j][2]), a3 = upk(acc[j][3]);
        lmx[j] = fmaxf(fmaxf(fmaxf(a0.x,a0.y),fmaxf(a1.x,a1.y)),
                       fmaxf(fmaxf(a2.x,a2.y),fmaxf(a3.x,a3.y)));
        lmn[j] = fminf(fminf(fminf(a0.x,a0.y),fminf(a1.x,a1.y)),
                       fminf(fminf(a2.x,a2.y),fminf(a3.x,a3.y)));
        ls[j] = ((a0.x+a0.y)+(a1.x+a1.y)) + ((a2.x+a2.y)+(a3.x+a3.y));
        float q0 = fmaf(a0.x,a0.x, fmaf(a0.y,a0.y, fmaf(a1.x,a1.x, a1.y*a1.y)));
        lq[j] = fmaf(a2.x,a2.x, fmaf(a2.y,a2.y, fmaf(a3.x,a3.x, fmaf(a3.y,a3.y, q0))));
    }
    #pragma unroll
    for (int j = 0; j < 8; j++){
        lmx[j] = fmaxf(lmx[j], __shfl_xor_sync(FULLM, lmx[j], 1));
        lmx[j] = fmaxf(lmx[j], __shfl_xor_sync(FULLM, lmx[j], 2));
        lmn[j] = fminf(lmn[j], __shfl_xor_sync(FULLM, lmn[j], 1));
        lmn[j] = fminf(lmn[j], __shfl_xor_sync(FULLM, lmn[j], 2));
        ls[j] += __shfl_xor_sync(FULLM, ls[j], 1);
        ls[j] += __shfl_xor_sync(FULLM, ls[j], 2);
        lq[j] += __shfl_xor_sync(FULLM, lq[j], 1);
        lq[j] += __shfl_xor_sync(FULLM, lq[j], 2);
    }
    if (kq == 0){
        #pragma unroll
        for (int j = 0; j < 8; j++){
            int co = half*64 + cog*8 + j;
            d_maxb[bs*C3 + co] = lmx[j];
            d_minb[bs*C3 + co] = lmn[j];
            atomicAdd(&ssum[co], ls[j]);
            atomicAdd(&ssq [co], lq[j]);
        }
    }
    __syncthreads();
    if (t < C3){
        d_ps2[blockIdx.x*C3 + t] = ssum[t];
        d_pq2[blockIdx.x*C3 + t] = ssq[t];
    }
}

// ---------------- final ----------------
__global__ void k_final(const float* __restrict__ g2, const float* __restrict__ b2,
                        float* __restrict__ out){
    int o = blockIdx.x*blockDim.x + threadIdx.x;
    if (o >= B_*C3*S_) return;
    int s  = o & (S_ - 1);
    int co = (o >> 12) & 127;
    int b  = o >> 19;
    float a = d_istd2[co]*g2[co];
    float base = fmaf(-d_mean2[co], a, b2[co]);
    int bs = b*S_ + s;
    float yv = (a > 0.f) ? d_maxb[bs*C3 + co] : ((a < 0.f) ? d_minb[bs*C3 + co] : 0.f);
    float r = fmaf(yv, a, base);
    out[B_*3*S_ + o] = r >= 0.f ? r : 0.1f*r;
}

extern "C" void kernel_launch(void* const* d_in, const int* in_sizes, int n_in,
                              void* d_out, int out_size){
    const float* xyz    = (const float*)d_in[0];
    const float* points = (const float*)d_in[1];
    const float* W0     = (const float*)d_in[2];
    const float* W1     = (const float*)d_in[3];
    const float* W2     = (const float*)d_in[4];
    const float* g0     = (const float*)d_in[5];
    const float* b0     = (const float*)d_in[6];
    const float* g1     = (const float*)d_in[7];
    const float* b1     = (const float*)d_in[8];
    const float* g2     = (const float*)d_in[9];
    const float* b2     = (const float*)d_in[10];
    float* out = (float*)d_out;

    const int smem0 = (4*C0*ST + C0*64) * 4;
    const int smem1 = (4*C1*ST + C1*64) * 4;
    const int smem2 = (2*C2*ST + C2*C3) * 4;
    cudaFuncSetAttribute(k_g0, cudaFuncAttributeMaxDynamicSharedMemorySize, smem0);
    cudaFuncSetAttribute(k_g1, cudaFuncAttributeMaxDynamicSharedMemorySize, smem1);
    cudaFuncSetAttribute(k_g2, cudaFuncAttributeMaxDynamicSharedMemorySize, smem2);

    k_tr  <<<dim3(N_/32, C1/32, B_), dim3(32,8)>>>(points);
    k_xyz <<<(B_*N_ + 255)/256, 256>>>(xyz, out);
    k_knn <<<(B_*S_/4)/4, 128>>>();
    k_g0  <<<B_*S_/4, 128, smem0>>>(W0);
    k_stats<<<64, 256>>>(0);
    k_g1  <<<B_*S_/4, 128, smem1>>>(W1, g0, b0);
    k_stats<<<64, 256>>>(1);
    k_g2  <<<B_*S_/2, 128, smem2>>>(W2, g1, b1);
    k_stats<<<128, 256>>>(2);
    k_final<<<(B_*C3*S_ + 255)/256, 256>>>(g2, b2, out);
}

// round 4
// speedup vs baseline: 1.2540x; 1.2540x over previous
#include <cuda_runtime.h>

#define B_ 2
#define N_ 16384
#define S_ 4096
#define K_ 32
#define C0 67
#define C1 64
#define C2 64
#define C3 128
#define ST 36
#define FULLM 0xffffffffu
#define FINF 3.402823466e38f

typedef unsigned long long ull;

__device__ __forceinline__ ull fma2(ull a, ull b, ull c){
    ull d;
    asm("fma.rn.f32x2 %0, %1, %2, %3;" : "=l"(d) : "l"(a), "l"(b), "l"(c));
    return d;
}
__device__ __forceinline__ ull pk(float lo, float hi){
    ull r; asm("mov.b64 %0, {%1,%2};" : "=l"(r) : "f"(lo), "f"(hi)); return r;
}
__device__ __forceinline__ float2 upk(ull v){
    float2 f; asm("mov.b64 {%0,%1}, %2;" : "=f"(f.x), "=f"(f.y) : "l"(v)); return f;
}

// ---------------- scratch ----------------
__device__ __align__(16) float  d_pt[B_*N_*C1];
__device__ __align__(16) float4 d_xyz4[B_*N_];
__device__              int     d_knn[B_*S_*K_];
__device__ __align__(16) float  d_buf0[(size_t)B_*S_*C1*K_];
__device__ __align__(16) float  d_buf1[(size_t)B_*S_*C2*K_];
__device__              float   d_maxb[B_*S_*C3];
__device__              float   d_minb[B_*S_*C3];
__device__              float   d_ps0[4096*C1], d_pq0[4096*C1];
__device__              float   d_ps1[4096*C2], d_pq1[4096*C2];
__device__              float   d_ps2[8192*C3], d_pq2[8192*C3];
__device__              float   d_mean0[C1], d_istd0[C1];
__device__              float   d_mean1[C2], d_istd1[C2];
__device__              float   d_mean2[C3], d_istd2[C3];

// ---------------- transpose points ----------------
__global__ void k_tr(const float* __restrict__ pts){
    __shared__ float tile[32][33];
    int b = blockIdx.z, c0 = blockIdx.y*32, n0 = blockIdx.x*32;
    for (int j = threadIdx.y; j < 32; j += 8)
        tile[j][threadIdx.x] = pts[((size_t)(b*C1 + c0 + j))*N_ + n0 + threadIdx.x];
    __syncthreads();
    for (int j = threadIdx.y; j < 32; j += 8)
        d_pt[((size_t)(b*N_ + n0 + j))*C1 + c0 + threadIdx.x] = tile[threadIdx.x][j];
}

// ---------------- xyz4 + new_xyz ----------------
__global__ void k_xyz(const float* __restrict__ xyz, float* __restrict__ out){
    int i = blockIdx.x*blockDim.x + threadIdx.x;
    if (i >= B_*N_) return;
    int b = i / N_, n = i % N_;
    float x = xyz[(b*3+0)*N_+n], y = xyz[(b*3+1)*N_+n], z = xyz[(b*3+2)*N_+n];
    d_xyz4[i] = make_float4(x, y, z, fmaf(z,z, fmaf(y,y, x*x)));
    if (n < S_){
        out[(b*3+0)*S_+n] = x;
        out[(b*3+1)*S_+n] = y;
        out[(b*3+2)*S_+n] = z;
    }
}

// ---------------- KNN: warp per query; block stages candidate tiles in smem ----------------
__global__ void __launch_bounds__(256) k_knn(){
    __shared__ float4 tile[512];
    int t = threadIdx.x;
    int lane = t & 31, w = t >> 5;
    int qg = blockIdx.x*8 + w;
    int b = qg >> 12;
    int s = qg & (S_ - 1);
    const float4* base = &d_xyz4[b*N_];
    float4 c4 = base[s];
    float cx = c4.x, cy = c4.y, cz = c4.z, cs = c4.w;

    // lane L holds L-th smallest distance among current top-32
    float bd = FINF;
    int   bi = 0;
    float cm = FINF;

    for (int j0 = 0; j0 < N_; j0 += 512){
        tile[t]       = base[j0 + t];
        tile[t + 256] = base[j0 + t + 256];
        __syncthreads();
        for (int c = 0; c < 16; c++){
            float4 p = tile[c*32 + lane];
            float d = (cs + p.w) - 2.0f*fmaf(cz,p.z, fmaf(cy,p.y, cx*p.x));
            unsigned m = __ballot_sync(FULLM, d < cm);
            while (m){
                int src = __ffs(m) - 1; m &= m - 1;
                float cd = __shfl_sync(FULLM, d, src);
                if (cd < cm){
                    int cn = j0 + c*32 + src;
                    float pk_ = __shfl_up_sync(FULLM, bd, 1);
                    int   pi_ = __shfl_up_sync(FULLM, bi, 1);
                    bool shift = (bd > cd);           // strict: stable vs ties
                    unsigned sm_ = __ballot_sync(FULLM, shift);
                    int first = __ffs(sm_) - 1;
                    if (shift){
                        if (lane == first){ bd = cd; bi = cn; }
                        else              { bd = pk_; bi = pi_; }
                    }
                    cm = __shfl_sync(FULLM, bd, 31);
                }
            }
        }
        __syncthreads();
    }
    d_knn[qg*K_ + lane] = bi;
}

// ---------------- layer0: gather + GEMM, 8x8 tile per thread, warp per point ----------------
__global__ void __launch_bounds__(128, 4) k_g0(const float* __restrict__ W0g){
    extern __shared__ float dyn[];
    float* sx = dyn;                 // 4 * C0 * ST
    float* sw = dyn + 4*C0*ST;       // C0 * 64
    __shared__ float ssum[C1], ssq[C1];
    int t = threadIdx.x;
    int bs0 = blockIdx.x*4;

    for (int e = t; e < C0*64; e += 128){
        int ci = e >> 6, co = e & 63;
        sw[e] = W0g[co*C0 + ci];
    }
    if (t < C1){ ssum[t] = 0.f; ssq[t] = 0.f; }

    { // gather: 1 thread per (point, k)
        int s_l = t >> 5, k = t & 31;
        int bs = bs0 + s_l;
        int b = bs / S_, s = bs % S_;
        int idx = d_knn[bs*K_ + k];
        float* xr = &sx[s_l*C0*ST];
        float4 pc = d_xyz4[b*N_ + s];
        float4 pn = d_xyz4[b*N_ + idx];
        xr[0*ST + k] = pn.x - pc.x;
        xr[1*ST + k] = pn.y - pc.y;
        xr[2*ST + k] = pn.z - pc.z;
        const float4* prow = (const float4*)&d_pt[((size_t)(b*N_ + idx))*C1];
        #pragma unroll
        for (int q = 0; q < 16; q++){
            float4 v = prow[q];
            int c = 3 + q*4;
            xr[(c+0)*ST + k] = v.x;
            xr[(c+1)*ST + k] = v.y;
            xr[(c+2)*ST + k] = v.z;
            xr[(c+3)*ST + k] = v.w;
        }
    }
    __syncthreads();

    int lane = t & 31, wp = t >> 5;
    int kq = lane & 3, cog = lane >> 2;
    const float* xb_ = &sx[wp*C0*ST + kq*8];
    const float* wb_ = sw + cog*8;
    ull acc[8][4];
    #pragma unroll
    for (int j = 0; j < 8; j++){ acc[j][0]=0; acc[j][1]=0; acc[j][2]=0; acc[j][3]=0; }

    for (int ci = 0; ci < C0; ci++){
        float4 xa = *(const float4*)(xb_ + ci*ST);
        float4 xc = *(const float4*)(xb_ + ci*ST + 4);
        ull x0 = pk(xa.x,xa.y), x1 = pk(xa.z,xa.w);
        ull x2 = pk(xc.x,xc.y), x3 = pk(xc.z,xc.w);
        float4 wa = *(const float4*)(wb_ + ci*64);
        float4 wc = *(const float4*)(wb_ + ci*64 + 4);
        float wv[8] = {wa.x,wa.y,wa.z,wa.w, wc.x,wc.y,wc.z,wc.w};
        #pragma unroll
        for (int j = 0; j < 8; j++){
            ull w2 = pk(wv[j], wv[j]);
            acc[j][0] = fma2(w2, x0, acc[j][0]);
            acc[j][1] = fma2(w2, x1, acc[j][1]);
            acc[j][2] = fma2(w2, x2, acc[j][2]);
            acc[j][3] = fma2(w2, x3, acc[j][3]);
        }
    }

    int bs = bs0 + wp;
    float* orow = &d_buf0[(size_t)bs*C1*K_];
    float ls[8], lq[8];
    #pragma unroll
    for (int j = 0; j < 8; j++){
        float2 a0 = upk(acc[j][0]), a1 = upk(acc[j][1]);
        float2 a2 = upk(acc[j][2]), a3 = upk(acc[j][3]);
        *(float4*)&orow[(cog*8+j)*K_ + kq*8]     = make_float4(a0.x,a0.y,a1.x,a1.y);
        *(float4*)&orow[(cog*8+j)*K_ + kq*8 + 4] = make_float4(a2.x,a2.y,a3.x,a3.y);
        ls[j] = ((a0.x+a0.y)+(a1.x+a1.y)) + ((a2.x+a2.y)+(a3.x+a3.y));
        float q0 = fmaf(a0.x,a0.x, fmaf(a0.y,a0.y, fmaf(a1.x,a1.x, a1.y*a1.y)));
        lq[j] = fmaf(a2.x,a2.x, fmaf(a2.y,a2.y, fmaf(a3.x,a3.x, fmaf(a3.y,a3.y, q0))));
    }
    #pragma unroll
    for (int j = 0; j < 8; j++){
        ls[j] += __shfl_xor_sync(FULLM, ls[j], 1);
        ls[j] += __shfl_xor_sync(FULLM, ls[j], 2);
        lq[j] += __shfl_xor_sync(FULLM, lq[j], 1);
        lq[j] += __shfl_xor_sync(FULLM, lq[j], 2);
    }
    if (kq == 0){
        #pragma unroll
        for (int j = 0; j < 8; j++){
            atomicAdd(&ssum[cog*8+j], ls[j]);
            atomicAdd(&ssq [cog*8+j], lq[j]);
        }
    }
    __syncthreads();
    if (t < C1){
        d_ps0[blockIdx.x*C1 + t] = ssum[t];
        d_pq0[blockIdx.x*C1 + t] = ssq[t];
    }
}

// ---------------- stats finalize ----------------
__global__ void k_stats(int which){
    const float *ps, *pq; float *mean, *istd; int nblk, C;
    if (which == 0){ ps = d_ps0; pq = d_pq0; mean = d_mean0; istd = d_istd0; nblk = 2048; C = 64; }
    else if (which == 1){ ps = d_ps1; pq = d_pq1; mean = d_mean1; istd = d_istd1; nblk = 2048; C = 64; }
    else { ps = d_ps2; pq = d_pq2; mean = d_mean2; istd = d_istd2; nblk = 4096; C = 128; }
    int c = blockIdx.x;
    __shared__ float rs[256], rq[256];
    float s = 0.f, q = 0.f;
    for (int i = threadIdx.x; i < nblk; i += 256){ s += ps[i*C + c]; q += pq[i*C + c]; }
    rs[threadIdx.x] = s; rq[threadIdx.x] = q;
    __syncthreads();
    for (int o = 128; o; o >>= 1){
        if (threadIdx.x < o){ rs[threadIdx.x] += rs[threadIdx.x+o]; rq[threadIdx.x] += rq[threadIdx.x+o]; }
        __syncthreads();
    }
    if (threadIdx.x == 0){
        float cnt = (float)(B_*S_*K_);
        float m = rs[0] / cnt;
        float v = rq[0] / cnt - m*m;
        mean[c] = m;
        istd[c] = rsqrtf(v + 1e-5f);
    }
}

// ---------------- layer1 ----------------
__global__ void __launch_bounds__(128, 4) k_g1(const float* __restrict__ W1g,
                     const float* __restrict__ g0, const float* __restrict__ b0){
    extern __shared__ float dyn[];
    float* sx = dyn;                 // 4 * C1 * ST
    float* sw = dyn + 4*C1*ST;       // C1 * 64
    __shared__ float ssum[C2], ssq[C2], sa[C1], sb[C1];
    int t = threadIdx.x;
    int bs0 = blockIdx.x*4;

    for (int e = t; e < C1*64; e += 128){
        int ci = e >> 6, co = e & 63;
        sw[e] = W1g[co*C1 + ci];
    }
    if (t < C1){
        float a = d_istd0[t]*g0[t];
        sa[t] = a;
        sb[t] = fmaf(-d_mean0[t], a, b0[t]);
        ssum[t] = 0.f; ssq[t] = 0.f;
    }
    __syncthreads();

    {
        const float4* src = (const float4*)&d_buf0[(size_t)bs0*C1*K_];
        for (int e = t; e < 2048; e += 128){
            float4 v = src[e];
            int p = e >> 9, r2 = e & 511;
            int ci = r2 >> 3, k4 = (r2 & 7)*4;
            float a = sa[ci], bb = sb[ci], r;
            r = fmaf(v.x,a,bb); v.x = r >= 0.f ? r : 0.1f*r;
            r = fmaf(v.y,a,bb); v.y = r >= 0.f ? r : 0.1f*r;
            r = fmaf(v.z,a,bb); v.z = r >= 0.f ? r : 0.1f*r;
            r = fmaf(v.w,a,bb); v.w = r >= 0.f ? r : 0.1f*r;
            *(float4*)&sx[p*C1*ST + ci*ST + k4] = v;
        }
    }
    __syncthreads();

    int lane = t & 31, wp = t >> 5;
    int kq = lane & 3, cog = lane >> 2;
    const float* xb_ = &sx[wp*C1*ST + kq*8];
    const float* wb_ = sw + cog*8;
    ull acc[8][4];
    #pragma unroll
    for (int j = 0; j < 8; j++){ acc[j][0]=0; acc[j][1]=0; acc[j][2]=0; acc[j][3]=0; }

    for (int ci = 0; ci < C1; ci++){
        float4 xa = *(const float4*)(xb_ + ci*ST);
        float4 xc = *(const float4*)(xb_ + ci*ST + 4);
        ull x0 = pk(xa.x,xa.y), x1 = pk(xa.z,xa.w);
        ull x2 = pk(xc.x,xc.y), x3 = pk(xc.z,xc.w);
        float4 wa = *(const float4*)(wb_ + ci*64);
        float4 wc = *(const float4*)(wb_ + ci*64 + 4);
        float wv[8] = {wa.x,wa.y,wa.z,wa.w, wc.x,wc.y,wc.z,wc.w};
        #pragma unroll
        for (int j = 0; j < 8; j++){
            ull w2 = pk(wv[j], wv[j]);
            acc[j][0] = fma2(w2, x0, acc[j][0]);
            acc[j][1] = fma2(w2, x1, acc[j][1]);
            acc[j][2] = fma2(w2, x2, acc[j][2]);
            acc[j][3] = fma2(w2, x3, acc[j][3]);
        }
    }

    int bs = bs0 + wp;
    float* orow = &d_buf1[(size_t)bs*C2*K_];
    float ls[8], lq[8];
    #pragma unroll
    for (int j = 0; j < 8; j++){
        float2 a0 = upk(acc[j][0]), a1 = upk(acc[j][1]);
        float2 a2 = upk(acc[j][2]), a3 = upk(acc[j][3]);
        *(float4*)&orow[(cog*8+j)*K_ + kq*8]     = make_float4(a0.x,a0.y,a1.x,a1.y);
        *(float4*)&orow[(cog*8+j)*K_ + kq*8 + 4] = make_float4(a2.x,a2.y,a3.x,a3.y);
        ls[j] = ((a0.x+a0.y)+(a1.x+a1.y)) + ((a2.x+a2.y)+(a3.x+a3.y));
        float q0 = fmaf(a0.x,a0.x, fmaf(a0.y,a0.y, fmaf(a1.x,a1.x, a1.y*a1.y)));
        lq[j] = fmaf(a2.x,a2.x, fmaf(a2.y,a2.y, fmaf(a3.x,a3.x, fmaf(a3.y,a3.y, q0))));
    }
    #pragma unroll
    for (int j = 0; j < 8; j++){
        ls[j] += __shfl_xor_sync(FULLM, ls[j], 1);
        ls[j] += __shfl_xor_sync(FULLM, ls[j], 2);
        lq[j] += __shfl_xor_sync(FULLM, lq[j], 1);
        lq[j] += __shfl_xor_sync(FULLM, lq[j], 2);
    }
    if (kq == 0){
        #pragma unroll
        for (int j = 0; j < 8; j++){
            atomicAdd(&ssum[cog*8+j], ls[j]);
            atomicAdd(&ssq [cog*8+j], lq[j]);
        }
    }
    __syncthreads();
    if (t < C2){
        d_ps1[blockIdx.x*C2 + t] = ssum[t];
        d_pq1[blockIdx.x*C2 + t] = ssq[t];
    }
}

// ---------------- layer2: 2 points/block, 2 warps/point, max/min over k ----------------
__global__ void __launch_bounds__(128, 4) k_g2(const float* __restrict__ W2g,
                     const float* __restrict__ g1, const float* __restrict__ b1){
    extern __shared__ float dyn[];
    float* sx = dyn;                 // 2 * C2 * ST
    float* sw = dyn + 2*C2*ST;       // C2 * 128
    __shared__ float sa[C2], sb[C2], ssum[C3], ssq[C3];
    int t = threadIdx.x;
    int bs0 = blockIdx.x*2;

    for (int e = t; e < C2*C3; e += 128){
        int ci = e >> 7, co = e & 127;
        sw[e] = W2g[co*C2 + ci];
    }
    if (t < C2){
        float a = d_istd1[t]*g1[t];
        sa[t] = a;
        sb[t] = fmaf(-d_mean1[t], a, b1[t]);
    }
    if (t < C3){ ssum[t] = 0.f; ssq[t] = 0.f; }
    __syncthreads();

    {
        const float4* src = (const float4*)&d_buf1[(size_t)bs0*C2*K_];
        for (int e = t; e < 1024; e += 128){
            float4 v = src[e];
            int p = e >> 9, r2 = e & 511;
            int ci = r2 >> 3, k4 = (r2 & 7)*4;
            float a = sa[ci], bb = sb[ci], r;
            r = fmaf(v.x,a,bb); v.x = r >= 0.f ? r : 0.1f*r;
            r = fmaf(v.y,a,bb); v.y = r >= 0.f ? r : 0.1f*r;
            r = fmaf(v.z,a,bb); v.z = r >= 0.f ? r : 0.1f*r;
            r = fmaf(v.w,a,bb); v.w = r >= 0.f ? r : 0.1f*r;
            *(float4*)&sx[p*C2*ST + ci*ST + k4] = v;
        }
    }
    __syncthreads();

    int lane = t & 31, wp = t >> 5;
    int pt = wp >> 1, half = wp & 1;
    int kq = lane & 3, cog = lane >> 2;
    const float* xb_ = &sx[pt*C2*ST + kq*8];
    const float* wb_ = sw + half*64 + cog*8;
    ull acc[8][4];
    #pragma unroll
    for (int j = 0; j < 8; j++){ acc[j][0]=0; acc[j][1]=0; acc[j][2]=0; acc[j][3]=0; }

    for (int ci = 0; ci < C2; ci++){
        float4 xa = *(const float4*)(xb_ + ci*ST);
        float4 xc = *(const float4*)(xb_ + ci*ST + 4);
        ull x0 = pk(xa.x,xa.y), x1 = pk(xa.z,xa.w);
        ull x2 = pk(xc.x,xc.y), x3 = pk(xc.z,xc.w);
        float4 wa = *(const float4*)(wb_ + ci*128);
        float4 wc = *(const float4*)(wb_ + ci*128 + 4);
        float wv[8] = {wa.x,wa.y,wa.z,wa.w, wc.x,wc.y,wc.z,wc.w};
        #pragma unroll
        for (int j = 0; j < 8; j++){
            ull w2 = pk(wv[j], wv[j]);
            acc[j][0] = fma2(w2, x0, acc[j][0]);
            acc[j][1] = fma2(w2, x1, acc[j][1]);
            acc[j][2] = fma2(w2, x2, acc[j][2]);
            acc[j][3] = fma2(w2, x3, acc[j][3]);
        }
    }

    int bs = bs0 + pt;
    float lmx[8], lmn[8], ls[8], lq[8];
    #pragma unroll
    for (int j = 0; j < 8; j++){
        float2 a0 = upk(acc[j][0]), a1 = upk(acc[j][1]);
        float2 a2 = upk(acc[j][2]), a3 = upk(acc[j][3]);
        lmx[j] = fmaxf(fmaxf(fmaxf(a0.x,a0.y),fmaxf(a1.x,a1.y)),
                       fmaxf(fmaxf(a2.x,a2.y),fmaxf(a3.x,a3.y)));
        lmn[j] = fminf(fminf(fminf(a0.x,a0.y),fminf(a1.x,a1.y)),
                       fminf(fminf(a2.x,a2.y),fminf(a3.x,a3.y)));
        ls[j] = ((a0.x+a0.y)+(a1.x+a1.y)) + ((a2.x+a2.y)+(a3.x+a3.y));
        float q0 = fmaf(a0.x,a0.x, fmaf(a0.y,a0.y, fmaf(a1.x,a1.x, a1.y*a1.y)));
        lq[j] = fmaf(a2.x,a2.x, fmaf(a2.y,a2.y, fmaf(a3.x,a3.x, fmaf(a3.y,a3.y, q0))));
    }
    #pragma unroll
    for (int j = 0; j < 8; j++){
        lmx[j] = fmaxf(lmx[j], __shfl_xor_sync(FULLM, lmx[j], 1));
        lmx[j] = fmaxf(lmx[j], __shfl_xor_sync(FULLM, lmx[j], 2));
        lmn[j] = fminf(lmn[j], __shfl_xor_sync(FULLM, lmn[j], 1));
        lmn[j] = fminf(lmn[j], __shfl_xor_sync(FULLM, lmn[j], 2));
        ls[j] += __shfl_xor_sync(FULLM, ls[j], 1);
        ls[j] += __shfl_xor_sync(FULLM, ls[j], 2);
        lq[j] += __shfl_xor_sync(FULLM, lq[j], 1);
        lq[j] += __shfl_xor_sync(FULLM, lq[j], 2);
    }
    if (kq == 0){
        #pragma unroll
        for (int j = 0; j < 8; j++){
            int co = half*64 + cog*8 + j;
            d_maxb[bs*C3 + co] = lmx[j];
            d_minb[bs*C3 + co] = lmn[j];
            atomicAdd(&ssum[co], ls[j]);
            atomicAdd(&ssq [co], lq[j]);
        }
    }
    __syncthreads();
    if (t < C3){
        d_ps2[blockIdx.x*C3 + t] = ssum[t];
        d_pq2[blockIdx.x*C3 + t] = ssq[t];
    }
}

// ---------------- final ----------------
__global__ void k_final(const float* __restrict__ g2, const float* __restrict__ b2,
                        float* __restrict__ out){
    int o = blockIdx.x*blockDim.x + threadIdx.x;
    if (o >= B_*C3*S_) return;
    int s  = o & (S_ - 1);
    int co = (o >> 12) & 127;
    int b  = o >> 19;
    float a = d_istd2[co]*g2[co];
    float base = fmaf(-d_mean2[co], a, b2[co]);
    int bs = b*S_ + s;
    float yv = (a > 0.f) ? d_maxb[bs*C3 + co] : ((a < 0.f) ? d_minb[bs*C3 + co] : 0.f);
    float r = fmaf(yv, a, base);
    out[B_*3*S_ + o] = r >= 0.f ? r : 0.1f*r;
}

extern "C" void kernel_launch(void* const* d_in, const int* in_sizes, int n_in,
                              void* d_out, int out_size){
    const float* xyz    = (const float*)d_in[0];
    const float* points = (const float*)d_in[1];
    const float* W0     = (const float*)d_in[2];
    const float* W1     = (const float*)d_in[3];
    const float* W2     = (const float*)d_in[4];
    const float* g0     = (const float*)d_in[5];
    const float* b0     = (const float*)d_in[6];
    const float* g1     = (const float*)d_in[7];
    const float* b1     = (const float*)d_in[8];
    const float* g2     = (const float*)d_in[9];
    const float* b2     = (const float*)d_in[10];
    float* out = (float*)d_out;

    const int smem0 = (4*C0*ST + C0*64) * 4;
    const int smem1 = (4*C1*ST + C1*64) * 4;
    const int smem2 = (2*C2*ST + C2*C3) * 4;
    cudaFuncSetAttribute(k_g0, cudaFuncAttributeMaxDynamicSharedMemorySize, smem0);
    cudaFuncSetAttribute(k_g1, cudaFuncAttributeMaxDynamicSharedMemorySize, smem1);
    cudaFuncSetAttribute(k_g2, cudaFuncAttributeMaxDynamicSharedMemorySize, smem2);

    k_tr  <<<dim3(N_/32, C1/32, B_), dim3(32,8)>>>(points);
    k_xyz <<<(B_*N_ + 255)/256, 256>>>(xyz, out);
    k_knn <<<B_*S_/8, 256>>>();
    k_g0  <<<B_*S_/4, 128, smem0>>>(W0);
    k_stats<<<64, 256>>>(0);
    k_g1  <<<B_*S_/4, 128, smem1>>>(W1, g0, b0);
    k_stats<<<64, 256>>>(1);
    k_g2  <<<B_*S_/2, 128, smem2>>>(W2, g1, b1);
    k_stats<<<128, 256>>>(2);
    k_final<<<(B_*C3*S_ + 255)/256, 256>>>(g2, b2, out);
}

// round 5
// speedup vs baseline: 1.2891x; 1.0279x over previous
#include <cuda_runtime.h>

#define B_ 2
#define N_ 16384
#define S_ 4096
#define K_ 32
#define C0 67
#define C1 64
#define C2 64
#define C3 128
#define ST 36
#define FULLM 0xffffffffu
#define FINF 3.402823466e38f

typedef unsigned long long ull;

__device__ __forceinline__ ull fma2(ull a, ull b, ull c){
    ull d;
    asm("fma.rn.f32x2 %0, %1, %2, %3;" : "=l"(d) : "l"(a), "l"(b), "l"(c));
    return d;
}
__device__ __forceinline__ ull pk(float lo, float hi){
    ull r; asm("mov.b64 %0, {%1,%2};" : "=l"(r) : "f"(lo), "f"(hi)); return r;
}
__device__ __forceinline__ float2 upk(ull v){
    float2 f; asm("mov.b64 {%0,%1}, %2;" : "=f"(f.x), "=f"(f.y) : "l"(v)); return f;
}

// ---------------- scratch ----------------
__device__ __align__(16) float  d_pt[B_*N_*C1];
__device__ __align__(16) float4 d_xyz4[B_*N_];
__device__              int     d_knn[B_*S_*K_];
__device__ __align__(16) float  d_buf0[(size_t)B_*S_*C1*K_];
__device__ __align__(16) float  d_buf1[(size_t)B_*S_*C2*K_];
__device__              float   d_maxb[B_*S_*C3];
__device__              float   d_minb[B_*S_*C3];
__device__              float   d_ps0[4096*C1], d_pq0[4096*C1];
__device__              float   d_ps1[4096*C2], d_pq1[4096*C2];
__device__              float   d_ps2[8192*C3], d_pq2[8192*C3];
__device__              float   d_mean0[C1], d_istd0[C1];
__device__              float   d_mean1[C2], d_istd1[C2];
__device__              float   d_mean2[C3], d_istd2[C3];

// ---------------- transpose points ----------------
__global__ void k_tr(const float* __restrict__ pts){
    __shared__ float tile[32][33];
    int b = blockIdx.z, c0 = blockIdx.y*32, n0 = blockIdx.x*32;
    for (int j = threadIdx.y; j < 32; j += 8)
        tile[j][threadIdx.x] = pts[((size_t)(b*C1 + c0 + j))*N_ + n0 + threadIdx.x];
    __syncthreads();
    for (int j = threadIdx.y; j < 32; j += 8)
        d_pt[((size_t)(b*N_ + n0 + j))*C1 + c0 + threadIdx.x] = tile[threadIdx.x][j];
}

// ---------------- xyz4 + new_xyz ----------------
__global__ void k_xyz(const float* __restrict__ xyz, float* __restrict__ out){
    int i = blockIdx.x*blockDim.x + threadIdx.x;
    if (i >= B_*N_) return;
    int b = i / N_, n = i % N_;
    float x = xyz[(b*3+0)*N_+n], y = xyz[(b*3+1)*N_+n], z = xyz[(b*3+2)*N_+n];
    d_xyz4[i] = make_float4(x, y, z, fmaf(z,z, fmaf(y,y, x*x)));
    if (n < S_){
        out[(b*3+0)*S_+n] = x;
        out[(b*3+1)*S_+n] = y;
        out[(b*3+2)*S_+n] = z;
    }
}

// ---------------- KNN: warp per query; smem tiles; short-chain insertion ----------------
__global__ void __launch_bounds__(256) k_knn(){
    __shared__ float4 tile[512];
    int t = threadIdx.x;
    int lane = t & 31, w = t >> 5;
    int qg = blockIdx.x*8 + w;
    int b = qg >> 12;
    int s = qg & (S_ - 1);
    const float4* base = &d_xyz4[b*N_];
    float4 c4 = base[s];
    float cx = c4.x, cy = c4.y, cz = c4.z, cs = c4.w;

    // lane L holds L-th smallest distance among current top-32
    float bd = FINF;
    int   bi = 0;
    float cm = FINF;     // may be stale-high; only used as ballot pre-filter

    for (int j0 = 0; j0 < N_; j0 += 512){
        tile[t]       = base[j0 + t];
        tile[t + 256] = base[j0 + t + 256];
        __syncthreads();
        for (int c = 0; c < 16; c++){
            float4 p = tile[c*32 + lane];
            float d = (cs + p.w) - 2.0f*fmaf(cz,p.z, fmaf(cy,p.y, cx*p.x));
            unsigned m = __ballot_sync(FULLM, d < cm);
            if (m){
                do {
                    int src = __ffs(m) - 1; m &= m - 1;
                    float cd = __shfl_sync(FULLM, d, src);
                    int   cn = j0 + c*32 + src;
                    float pk_ = __shfl_up_sync(FULLM, bd, 1);
                    int   pi_ = __shfl_up_sync(FULLM, bi, 1);
                    if (lane == 0) pk_ = -FINF;
                    if (bd > cd){                 // insert (no-op if cd >= bd[31])
                        bool f = (pk_ <= cd);     // this lane is the insertion point
                        bd = f ? cd : pk_;
                        bi = f ? cn : pi_;
                    }
                } while (m);
                cm = __shfl_sync(FULLM, bd, 31);  // refresh filter once per group
            }
        }
        __syncthreads();
    }
    d_knn[qg*K_ + lane] = bi;
}

// ---------------- layer0: gather + GEMM, 8x8 tile per thread, warp per point ----------------
__global__ void __launch_bounds__(128, 4) k_g0(const float* __restrict__ W0g){
    extern __shared__ float dyn[];
    float* sx = dyn;                 // 4 * C0 * ST
    float* sw = dyn + 4*C0*ST;       // C0 * 64
    __shared__ float ssum[C1], ssq[C1];
    int t = threadIdx.x;
    int bs0 = blockIdx.x*4;

    for (int e = t; e < C0*64; e += 128){
        int ci = e >> 6, co = e & 63;
        sw[e] = W0g[co*C0 + ci];
    }
    if (t < C1){ ssum[t] = 0.f; ssq[t] = 0.f; }

    { // gather: 1 thread per (point, k)
        int s_l = t >> 5, k = t & 31;
        int bs = bs0 + s_l;
        int b = bs / S_, s = bs % S_;
        int idx = d_knn[bs*K_ + k];
        float* xr = &sx[s_l*C0*ST];
        float4 pc = d_xyz4[b*N_ + s];
        float4 pn = d_xyz4[b*N_ + idx];
        xr[0*ST + k] = pn.x - pc.x;
        xr[1*ST + k] = pn.y - pc.y;
        xr[2*ST + k] = pn.z - pc.z;
        const float4* prow = (const float4*)&d_pt[((size_t)(b*N_ + idx))*C1];
        #pragma unroll
        for (int q = 0; q < 16; q++){
            float4 v = prow[q];
            int c = 3 + q*4;
            xr[(c+0)*ST + k] = v.x;
            xr[(c+1)*ST + k] = v.y;
            xr[(c+2)*ST + k] = v.z;
            xr[(c+3)*ST + k] = v.w;
        }
    }
    __syncthreads();

    int lane = t & 31, wp = t >> 5;
    int kq = lane & 3, cog = lane >> 2;
    const float* xb_ = &sx[wp*C0*ST + kq*8];
    const float* wb_ = sw + cog*8;
    ull acc[8][4];
    #pragma unroll
    for (int j = 0; j < 8; j++){ acc[j][0]=0; acc[j][1]=0; acc[j][2]=0; acc[j][3]=0; }

    for (int ci = 0; ci < C0; ci++){
        float4 xa = *(const float4*)(xb_ + ci*ST);
        float4 xc = *(const float4*)(xb_ + ci*ST + 4);
        ull x0 = pk(xa.x,xa.y), x1 = pk(xa.z,xa.w);
        ull x2 = pk(xc.x,xc.y), x3 = pk(xc.z,xc.w);
        float4 wa = *(const float4*)(wb_ + ci*64);
        float4 wc = *(const float4*)(wb_ + ci*64 + 4);
        float wv[8] = {wa.x,wa.y,wa.z,wa.w, wc.x,wc.y,wc.z,wc.w};
        #pragma unroll
        for (int j = 0; j < 8; j++){
            ull w2 = pk(wv[j], wv[j]);
            acc[j][0] = fma2(w2, x0, acc[j][0]);
            acc[j][1] = fma2(w2, x1, acc[j][1]);
            acc[j][2] = fma2(w2, x2, acc[j][2]);
            acc[j][3] = fma2(w2, x3, acc[j][3]);
        }
    }

    int bs = bs0 + wp;
    float* orow = &d_buf0[(size_t)bs*C1*K_];
    float ls[8], lq[8];
    #pragma unroll
    for (int j = 0; j < 8; j++){
        float2 a0 = upk(acc[j][0]), a1 = upk(acc[j][1]);
        float2 a2 = upk(acc[j][2]), a3 = upk(acc[j][3]);
        *(float4*)&orow[(cog*8+j)*K_ + kq*8]     = make_float4(a0.x,a0.y,a1.x,a1.y);
        *(float4*)&orow[(cog*8+j)*K_ + kq*8 + 4] = make_float4(a2.x,a2.y,a3.x,a3.y);
        ls[j] = ((a0.x+a0.y)+(a1.x+a1.y)) + ((a2.x+a2.y)+(a3.x+a3.y));
        float q0 = fmaf(a0.x,a0.x, fmaf(a0.y,a0.y, fmaf(a1.x,a1.x, a1.y*a1.y)));
        lq[j] = fmaf(a2.x,a2.x, fmaf(a2.y,a2.y, fmaf(a3.x,a3.x, fmaf(a3.y,a3.y, q0))));
    }
    #pragma unroll
    for (int j = 0; j < 8; j++){
        ls[j] += __shfl_xor_sync(FULLM, ls[j], 1);
        ls[j] += __shfl_xor_sync(FULLM, ls[j], 2);
        lq[j] += __shfl_xor_sync(FULLM, lq[j], 1);
        lq[j] += __shfl_xor_sync(FULLM, lq[j], 2);
    }
    if (kq == 0){
        #pragma unroll
        for (int j = 0; j < 8; j++){
            atomicAdd(&ssum[cog*8+j], ls[j]);
            atomicAdd(&ssq [cog*8+j], lq[j]);
        }
    }
    __syncthreads();
    if (t < C1){
        d_ps0[blockIdx.x*C1 + t] = ssum[t];
        d_pq0[blockIdx.x*C1 + t] = ssq[t];
    }
}

// ---------------- stats finalize ----------------
__global__ void k_stats(int which){
    const float *ps, *pq; float *mean, *istd; int nblk, C;
    if (which == 0){ ps = d_ps0; pq = d_pq0; mean = d_mean0; istd = d_istd0; nblk = 2048; C = 64; }
    else if (which == 1){ ps = d_ps1; pq = d_pq1; mean = d_mean1; istd = d_istd1; nblk = 2048; C = 64; }
    else { ps = d_ps2; pq = d_pq2; mean = d_mean2; istd = d_istd2; nblk = 4096; C = 128; }
    int c = blockIdx.x;
    __shared__ float rs[256], rq[256];
    float s = 0.f, q = 0.f;
    for (int i = threadIdx.x; i < nblk; i += 256){ s += ps[i*C + c]; q += pq[i*C + c]; }
    rs[threadIdx.x] = s; rq[threadIdx.x] = q;
    __syncthreads();
    for (int o = 128; o; o >>= 1){
        if (threadIdx.x < o){ rs[threadIdx.x] += rs[threadIdx.x+o]; rq[threadIdx.x] += rq[threadIdx.x+o]; }
        __syncthreads();
    }
    if (threadIdx.x == 0){
        float cnt = (float)(B_*S_*K_);
        float m = rs[0] / cnt;
        float v = rq[0] / cnt - m*m;
        mean[c] = m;
        istd[c] = rsqrtf(v + 1e-5f);
    }
}

// ---------------- layer1 ----------------
__global__ void __launch_bounds__(128, 4) k_g1(const float* __restrict__ W1g,
                     const float* __restrict__ g0, const float* __restrict__ b0){
    extern __shared__ float dyn[];
    float* sx = dyn;                 // 4 * C1 * ST
    float* sw = dyn + 4*C1*ST;       // C1 * 64
    __shared__ float ssum[C2], ssq[C2], sa[C1], sb[C1];
    int t = threadIdx.x;
    int bs0 = blockIdx.x*4;

    for (int e = t; e < C1*64; e += 128){
        int ci = e >> 6, co = e & 63;
        sw[e] = W1g[co*C1 + ci];
    }
    if (t < C1){
        float a = d_istd0[t]*g0[t];
        sa[t] = a;
        sb[t] = fmaf(-d_mean0[t], a, b0[t]);
        ssum[t] = 0.f; ssq[t] = 0.f;
    }
    __syncthreads();

    {
        const float4* src = (const float4*)&d_buf0[(size_t)bs0*C1*K_];
        for (int e = t; e < 2048; e += 128){
            float4 v = src[e];
            int p = e >> 9, r2 = e & 511;
            int ci = r2 >> 3, k4 = (r2 & 7)*4;
            float a = sa[ci], bb = sb[ci], r;
            r = fmaf(v.x,a,bb); v.x = r >= 0.f ? r : 0.1f*r;
            r = fmaf(v.y,a,bb); v.y = r >= 0.f ? r : 0.1f*r;
            r = fmaf(v.z,a,bb); v.z = r >= 0.f ? r : 0.1f*r;
            r = fmaf(v.w,a,bb); v.w = r >= 0.f ? r : 0.1f*r;
            *(float4*)&sx[p*C1*ST + ci*ST + k4] = v;
        }
    }
    __syncthreads();

    int lane = t & 31, wp = t >> 5;
    int kq = lane & 3, cog = lane >> 2;
    const float* xb_ = &sx[wp*C1*ST + kq*8];
    const float* wb_ = sw + cog*8;
    ull acc[8][4];
    #pragma unroll
    for (int j = 0; j < 8; j++){ acc[j][0]=0; acc[j][1]=0; acc[j][2]=0; acc[j][3]=0; }

    for (int ci = 0; ci < C1; ci++){
        float4 xa = *(const float4*)(xb_ + ci*ST);
        float4 xc = *(const float4*)(xb_ + ci*ST + 4);
        ull x0 = pk(xa.x,xa.y), x1 = pk(xa.z,xa.w);
        ull x2 = pk(xc.x,xc.y), x3 = pk(xc.z,xc.w);
        float4 wa = *(const float4*)(wb_ + ci*64);
        float4 wc = *(const float4*)(wb_ + ci*64 + 4);
        float wv[8] = {wa.x,wa.y,wa.z,wa.w, wc.x,wc.y,wc.z,wc.w};
        #pragma unroll
        for (int j = 0; j < 8; j++){
            ull w2 = pk(wv[j], wv[j]);
            acc[j][0] = fma2(w2, x0, acc[j][0]);
            acc[j][1] = fma2(w2, x1, acc[j][1]);
            acc[j][2] = fma2(w2, x2, acc[j][2]);
            acc[j][3] = fma2(w2, x3, acc[j][3]);
        }
    }

    int bs = bs0 + wp;
    float* orow = &d_buf1[(size_t)bs*C2*K_];
    float ls[8], lq[8];
    #pragma unroll
    for (int j = 0; j < 8; j++){
        float2 a0 = upk(acc[j][0]), a1 = upk(acc[j][1]);
        float2 a2 = upk(acc[j][2]), a3 = upk(acc[j][3]);
        *(float4*)&orow[(cog*8+j)*K_ + kq*8]     = make_float4(a0.x,a0.y,a1.x,a1.y);
        *(float4*)&orow[(cog*8+j)*K_ + kq*8 + 4] = make_float4(a2.x,a2.y,a3.x,a3.y);
        ls[j] = ((a0.x+a0.y)+(a1.x+a1.y)) + ((a2.x+a2.y)+(a3.x+a3.y));
        float q0 = fmaf(a0.x,a0.x, fmaf(a0.y,a0.y, fmaf(a1.x,a1.x, a1.y*a1.y)));
        lq[j] = fmaf(a2.x,a2.x, fmaf(a2.y,a2.y, fmaf(a3.x,a3.x, fmaf(a3.y,a3.y, q0))));
    }
    #pragma unroll
    for (int j = 0; j < 8; j++){
        ls[j] += __shfl_xor_sync(FULLM, ls[j], 1);
        ls[j] += __shfl_xor_sync(FULLM, ls[j], 2);
        lq[j] += __shfl_xor_sync(FULLM, lq[j], 1);
        lq[j] += __shfl_xor_sync(FULLM, lq[j], 2);
    }
    if (kq == 0){
        #pragma unroll
        for (int j = 0; j < 8; j++){
            atomicAdd(&ssum[cog*8+j], ls[j]);
            atomicAdd(&ssq [cog*8+j], lq[j]);
        }
    }
    __syncthreads();
    if (t < C2){
        d_ps1[blockIdx.x*C2 + t] = ssum[t];
        d_pq1[blockIdx.x*C2 + t] = ssq[t];
    }
}

// ---------------- layer2: 2 points/block, 2 warps/point, max/min over k ----------------
__global__ void __launch_bounds__(128, 4) k_g2(const float* __restrict__ W2g,
                     const float* __restrict__ g1, const float* __restrict__ b1){
    extern __shared__ float dyn[];
    float* sx = dyn;                 // 2 * C2 * ST
    float* sw = dyn + 2*C2*ST;       // C2 * 128
    __shared__ float sa[C2], sb[C2], ssum[C3], ssq[C3];
    int t = threadIdx.x;
    int bs0 = blockIdx.x*2;

    for (int e = t; e < C2*C3; e += 128){
        int ci = e >> 7, co = e & 127;
        sw[e] = W2g[co*C2 + ci];
    }
    if (t < C2){
        float a = d_istd1[t]*g1[t];
        sa[t] = a;
        sb[t] = fmaf(-d_mean1[t], a, b1[t]);
    }
    if (t < C3){ ssum[t] = 0.f; ssq[t] = 0.f; }
    __syncthreads();

    {
        const float4* src = (const float4*)&d_buf1[(size_t)bs0*C2*K_];
        for (int e = t; e < 1024; e += 128){
            float4 v = src[e];
            int p = e >> 9, r2 = e & 511;
            int ci = r2 >> 3, k4 = (r2 & 7)*4;
            float a = sa[ci], bb = sb[ci], r;
            r = fmaf(v.x,a,bb); v.x = r >= 0.f ? r : 0.1f*r;
            r = fmaf(v.y,a,bb); v.y = r >= 0.f ? r : 0.1f*r;
            r = fmaf(v.z,a,bb); v.z = r >= 0.f ? r : 0.1f*r;
            r = fmaf(v.w,a,bb); v.w = r >= 0.f ? r : 0.1f*r;
            *(float4*)&sx[p*C2*ST + ci*ST + k4] = v;
        }
    }
    __syncthreads();

    int lane = t & 31, wp = t >> 5;
    int pt = wp >> 1, half = wp & 1;
    int kq = lane & 3, cog = lane >> 2;
    const float* xb_ = &sx[pt*C2*ST + kq*8];
    const float* wb_ = sw + half*64 + cog*8;
    ull acc[8][4];
    #pragma unroll
    for (int j = 0; j < 8; j++){ acc[j][0]=0; acc[j][1]=0; acc[j][2]=0; acc[j][3]=0; }

    for (int ci = 0; ci < C2; ci++){
        float4 xa = *(const float4*)(xb_ + ci*ST);
        float4 xc = *(const float4*)(xb_ + ci*ST + 4);
        ull x0 = pk(xa.x,xa.y), x1 = pk(xa.z,xa.w);
        ull x2 = pk(xc.x,xc.y), x3 = pk(xc.z,xc.w);
        float4 wa = *(const float4*)(wb_ + ci*128);
        float4 wc = *(const float4*)(wb_ + ci*128 + 4);
        float wv[8] = {wa.x,wa.y,wa.z,wa.w, wc.x,wc.y,wc.z,wc.w};
        #pragma unroll
        for (int j = 0; j < 8; j++){
            ull w2 = pk(wv[j], wv[j]);
            acc[j][0] = fma2(w2, x0, acc[j][0]);
            acc[j][1] = fma2(w2, x1, acc[j][1]);
            acc[j][2] = fma2(w2, x2, acc[j][2]);
            acc[j][3] = fma2(w2, x3, acc[j][3]);
        }
    }

    int bs = bs0 + pt;
    float lmx[8], lmn[8], ls[8], lq[8];
    #pragma unroll
    for (int j = 0; j < 8; j++){
        float2 a0 = upk(acc[j][0]), a1 = upk(acc[j][1]);
        float2 a2 = upk(acc[j][2]), a3 = upk(acc[j][3]);
        lmx[j] = fmaxf(fmaxf(fmaxf(a0.x,a0.y),fmaxf(a1.x,a1.y)),
                       fmaxf(fmaxf(a2.x,a2.y),fmaxf(a3.x,a3.y)));
        lmn[j] = fminf(fminf(fminf(a0.x,a0.y),fminf(a1.x,a1.y)),
                       fminf(fminf(a2.x,a2.y),fminf(a3.x,a3.y)));
        ls[j] = ((a0.x+a0.y)+(a1.x+a1.y)) + ((a2.x+a2.y)+(a3.x+a3.y));
        float q0 = fmaf(a0.x,a0.x, fmaf(a0.y,a0.y, fmaf(a1.x,a1.x, a1.y*a1.y)));
        lq[j] = fmaf(a2.x,a2.x, fmaf(a2.y,a2.y, fmaf(a3.x,a3.x, fmaf(a3.y,a3.y, q0))));
    }
    #pragma unroll
    for (int j = 0; j < 8; j++){
        lmx[j] = fmaxf(lmx[j], __shfl_xor_sync(FULLM, lmx[j], 1));
        lmx[j] = fmaxf(lmx[j], __shfl_xor_sync(FULLM, lmx[j], 2));
        lmn[j] = fminf(lmn[j], __shfl_xor_sync(FULLM, lmn[j], 1));
        lmn[j] = fminf(lmn[j], __shfl_xor_sync(FULLM, lmn[j], 2));
        ls[j] += __shfl_xor_sync(FULLM, ls[j], 1);
        ls[j] += __shfl_xor_sync(FULLM, ls[j], 2);
        lq[j] += __shfl_xor_sync(FULLM, lq[j], 1);
        lq[j] += __shfl_xor_sync(FULLM, lq[j], 2);
    }
    if (kq == 0){
        #pragma unroll
        for (int j = 0; j < 8; j++){
            int co = half*64 + cog*8 + j;
            d_maxb[bs*C3 + co] = lmx[j];
            d_minb[bs*C3 + co] = lmn[j];
            atomicAdd(&ssum[co], ls[j]);
            atomicAdd(&ssq [co], lq[j]);
        }
    }
    __syncthreads();
    if (t < C3){
        d_ps2[blockIdx.x*C3 + t] = ssum[t];
        d_pq2[blockIdx.x*C3 + t] = ssq[t];
    }
}

// ---------------- final ----------------
__global__ void k_final(const float* __restrict__ g2, const float* __restrict__ b2,
                        float* __restrict__ out){
    int o = blockIdx.x*blockDim.x + threadIdx.x;
    if (o >= B_*C3*S_) return;
    int s  = o & (S_ - 1);
    int co = (o >> 12) & 127;
    int b  = o >> 19;
    float a = d_istd2[co]*g2[co];
    float base = fmaf(-d_mean2[co], a, b2[co]);
    int bs = b*S_ + s;
    float yv = (a > 0.f) ? d_maxb[bs*C3 + co] : ((a < 0.f) ? d_minb[bs*C3 + co] : 0.f);
    float r = fmaf(yv, a, base);
    out[B_*3*S_ + o] = r >= 0.f ? r : 0.1f*r;
}

extern "C" void kernel_launch(void* const* d_in, const int* in_sizes, int n_in,
                              void* d_out, int out_size){
    const float* xyz    = (const float*)d_in[0];
    const float* points = (const float*)d_in[1];
    const float* W0     = (const float*)d_in[2];
    const float* W1     = (const float*)d_in[3];
    const float* W2     = (const float*)d_in[4];
    const float* g0     = (const float*)d_in[5];
    const float* b0     = (const float*)d_in[6];
    const float* g1     = (const float*)d_in[7];
    const float* b1     = (const float*)d_in[8];
    const float* g2     = (const float*)d_in[9];
    const float* b2     = (const float*)d_in[10];
    float* out = (float*)d_out;

    const int smem0 = (4*C0*ST + C0*64) * 4;
    const int smem1 = (4*C1*ST + C1*64) * 4;
    const int smem2 = (2*C2*ST + C2*C3) * 4;
    cudaFuncSetAttribute(k_g0, cudaFuncAttributeMaxDynamicSharedMemorySize, smem0);
    cudaFuncSetAttribute(k_g1, cudaFuncAttributeMaxDynamicSharedMemorySize, smem1);
    cudaFuncSetAttribute(k_g2, cudaFuncAttributeMaxDynamicSharedMemorySize, smem2);

    k_tr  <<<dim3(N_/32, C1/32, B_), dim3(32,8)>>>(points);
    k_xyz <<<(B_*N_ + 255)/256, 256>>>(xyz, out);
    k_knn <<<B_*S_/8, 256>>>();
    k_g0  <<<B_*S_/4, 128, smem0>>>(W0);
    k_stats<<<64, 256>>>(0);
    k_g1  <<<B_*S_/4, 128, smem1>>>(W1, g0, b0);
    k_stats<<<64, 256>>>(1);
    k_g2  <<<B_*S_/2, 128, smem2>>>(W2, g1, b1);
    k_stats<<<128, 256>>>(2);
    k_final<<<(B_*C3*S_ + 255)/256, 256>>>(g2, b2, out);
}